// round 6
// baseline (speedup 1.0000x reference)
#include <cuda_runtime.h>

// LSTM seq2seq: B=65536, H=64, IN=9, enc 7 steps, dec 10 steps + FC(64->9).
// R=2 batch elements per thread: each broadcast weight load (LDS.128) feeds
// 4 packed fma.rn.f32x2 -> fma-pipe-bound instead of smem-crossbar-bound.

#define BTOT    65536
#define H       64
#define IN      9
#define SRCLEN  7
#define PREDLEN 10
#define G4      256      // 4*H gate rows
#define WSTR    76       // padded row: [x:9][bias:1][h:64][pad:2] (19 x 16B)
#define NPAIR   38       // WSTR/2
#define NCHUNK  19       // WSTR/4 (16B chunks)
#define TPB     128
#define EPB     256      // elements per block (R=2)

typedef unsigned long long ull;

__device__ __forceinline__ ull pack2(float lo, float hi) {
    ull r; asm("mov.b64 %0, {%1, %2};" : "=l"(r) : "f"(lo), "f"(hi)); return r;
}
__device__ __forceinline__ void unpack2(ull p, float &lo, float &hi) {
    asm("mov.b64 {%0, %1}, %2;" : "=f"(lo), "=f"(hi) : "l"(p));
}
__device__ __forceinline__ void ffma2(ull &acc, ull a, ull b) {
    asm("fma.rn.f32x2 %0, %1, %2, %0;" : "+l"(acc) : "l"(a), "l"(b));
}
__device__ __forceinline__ float psum(ull p) {
    float lo, hi; unpack2(p, lo, hi); return lo + hi;
}

__device__ __forceinline__ float fast_tanh(float x) {
    float y; asm("tanh.approx.f32 %0, %1;" : "=f"(y) : "f"(x)); return y;
}
__device__ __forceinline__ float fast_sigmoid(float x) {
    return fmaf(0.5f, fast_tanh(0.5f * x), 0.5f);
}

// smem layout (floats)
#define OFF_W    0
#define OFF_C    (G4 * WSTR)                 // 19456
#define OFF_HB   (OFF_C + H * EPB)           // +16384
#define OFF_FCW  (OFF_HB + H * EPB)          // +16384
#define OFF_FCB  (OFF_FCW + IN * H)          // +576
#define SMEM_FLOATS (OFF_FCB + 16)
#define SMEM_BYTES  (SMEM_FLOATS * 4)        // 211,264 B

__device__ __forceinline__ void lstm_step(const float* __restrict__ w,
                                          float* __restrict__ cbuf,
                                          float* __restrict__ hb,
                                          ull (&sA)[NPAIR], ull (&sB)[NPAIR],
                                          int tid)
{
    #pragma unroll 1
    for (int j = 0; j < H; j++) {
        const float* r0 = w + j * WSTR;
        const float* r1 = r0 + 64  * WSTR;
        const float* r2 = r0 + 128 * WSTR;
        const float* r3 = r0 + 192 * WSTR;
        ull a0A = 0, a1A = 0, a2A = 0, a3A = 0;
        ull a0B = 0, a1B = 0, a2B = 0, a3B = 0;
        #pragma unroll
        for (int p = 0; p < NCHUNK; p++) {
            ulonglong2 q0 = *(const ulonglong2*)(r0 + 4 * p);
            ffma2(a0A, sA[2*p], q0.x); ffma2(a0A, sA[2*p+1], q0.y);
            ffma2(a0B, sB[2*p], q0.x); ffma2(a0B, sB[2*p+1], q0.y);
            ulonglong2 q1 = *(const ulonglong2*)(r1 + 4 * p);
            ffma2(a1A, sA[2*p], q1.x); ffma2(a1A, sA[2*p+1], q1.y);
            ffma2(a1B, sB[2*p], q1.x); ffma2(a1B, sB[2*p+1], q1.y);
            ulonglong2 q2 = *(const ulonglong2*)(r2 + 4 * p);
            ffma2(a2A, sA[2*p], q2.x); ffma2(a2A, sA[2*p+1], q2.y);
            ffma2(a2B, sB[2*p], q2.x); ffma2(a2B, sB[2*p+1], q2.y);
            ulonglong2 q3 = *(const ulonglong2*)(r3 + 4 * p);
            ffma2(a3A, sA[2*p], q3.x); ffma2(a3A, sA[2*p+1], q3.y);
            ffma2(a3B, sB[2*p], q3.x); ffma2(a3B, sB[2*p+1], q3.y);
        }
        // element A
        {
            float ig = fast_sigmoid(psum(a0A));
            float fg = fast_sigmoid(psum(a1A));
            float g  = fast_tanh(psum(a2A));
            float og = fast_sigmoid(psum(a3A));
            float c  = cbuf[j * EPB + tid];
            c = fg * c + ig * g;
            cbuf[j * EPB + tid] = c;
            float hn = og * fast_tanh(c);
            hb[(((j >> 1) * EPB + tid) << 1) | (j & 1)] = hn;
        }
        // element B
        {
            float ig = fast_sigmoid(psum(a0B));
            float fg = fast_sigmoid(psum(a1B));
            float g  = fast_tanh(psum(a2B));
            float og = fast_sigmoid(psum(a3B));
            float c  = cbuf[j * EPB + tid + TPB];
            c = fg * c + ig * g;
            cbuf[j * EPB + tid + TPB] = c;
            float hn = og * fast_tanh(c);
            hb[(((j >> 1) * EPB + tid + TPB) << 1) | (j & 1)] = hn;
        }
    }
    // reload new h into packed register pairs (constant-indexed)
    #pragma unroll
    for (int p = 0; p < H / 2; p++) {
        sA[5 + p] = *(const ull*)(hb + ((p * EPB + tid) << 1));
        sB[5 + p] = *(const ull*)(hb + ((p * EPB + tid + TPB) << 1));
    }
}

__global__ void __launch_bounds__(TPB, 1)
lstm_seq2seq_kernel(const float* __restrict__ src,
                    const float* __restrict__ eWih, const float* __restrict__ eWhh,
                    const float* __restrict__ eb,
                    const float* __restrict__ dWih, const float* __restrict__ dWhh,
                    const float* __restrict__ db,
                    const float* __restrict__ fcW,  const float* __restrict__ fcbg,
                    float* __restrict__ out)
{
    extern __shared__ float smem[];
    float* w    = smem + OFF_W;
    float* cbuf = smem + OFF_C;
    float* hb   = smem + OFF_HB;
    float* fcw  = smem + OFF_FCW;
    float* fcb  = smem + OFF_FCB;

    const int tid = threadIdx.x;
    const int eA  = blockIdx.x * EPB + tid;        // element A
    const int eB  = eA + TPB;                      // element B

    // ---- load encoder weights into fused row layout (2 rows per thread) ----
    #pragma unroll
    for (int rr = 0; rr < 2; rr++) {
        const int r = tid + rr * TPB;
        float* wr = w + r * WSTR;
        #pragma unroll
        for (int k = 0; k < IN; k++) wr[k] = eWih[r * IN + k];
        wr[9] = eb[r];
        #pragma unroll
        for (int k = 0; k < H; k++) wr[10 + k] = eWhh[r * H + k];
        wr[74] = 0.0f; wr[75] = 0.0f;
    }
    // init c = 0
    #pragma unroll 1
    for (int j = 0; j < H; j++) {
        cbuf[j * EPB + tid] = 0.0f;
        cbuf[j * EPB + tid + TPB] = 0.0f;
    }
    __syncthreads();

    // packed state: pairs 0..4 = [x0..x8, 1], pairs 5..36 = h, pair 37 = 0
    ull sA[NPAIR], sB[NPAIR];
    #pragma unroll
    for (int p = 0; p < NPAIR; p++) { sA[p] = 0ull; sB[p] = 0ull; }

    const float* xpA = src + (size_t)eA * (SRCLEN * IN);
    const float* xpB = src + (size_t)eB * (SRCLEN * IN);

    // ---- encoder ----
    #pragma unroll 1
    for (int t = 0; t < SRCLEN; t++) {
        float xa[IN], xb[IN];
        #pragma unroll
        for (int k = 0; k < IN; k++) { xa[k] = xpA[t * IN + k]; xb[k] = xpB[t * IN + k]; }
        sA[0] = pack2(xa[0], xa[1]); sA[1] = pack2(xa[2], xa[3]);
        sA[2] = pack2(xa[4], xa[5]); sA[3] = pack2(xa[6], xa[7]);
        sA[4] = pack2(xa[8], 1.0f);
        sB[0] = pack2(xb[0], xb[1]); sB[1] = pack2(xb[2], xb[3]);
        sB[2] = pack2(xb[4], xb[5]); sB[3] = pack2(xb[6], xb[7]);
        sB[4] = pack2(xb[8], 1.0f);
        lstm_step(w, cbuf, hb, sA, sB, tid);
    }

    // ---- swap in decoder weights ----
    __syncthreads();
    #pragma unroll
    for (int rr = 0; rr < 2; rr++) {
        const int r = tid + rr * TPB;
        float* wr = w + r * WSTR;
        #pragma unroll
        for (int k = 0; k < IN; k++) wr[k] = dWih[r * IN + k];
        wr[9] = db[r];
        #pragma unroll
        for (int k = 0; k < H; k++) wr[10 + k] = dWhh[r * H + k];
        wr[74] = 0.0f; wr[75] = 0.0f;
    }
    for (int idx = tid; idx < IN * H; idx += TPB) fcw[idx] = fcW[idx];
    if (tid < IN) fcb[tid] = fcbg[tid];
    __syncthreads();

    // decoder first input = src[:, -1, :] — already resident in sA/sB[0..4]
    float* outA = out + (size_t)eA * (PREDLEN * IN);
    float* outB = out + (size_t)eB * (PREDLEN * IN);

    // ---- decoder ----
    #pragma unroll 1
    for (int t = 0; t < PREDLEN; t++) {
        lstm_step(w, cbuf, hb, sA, sB, tid);
        float prA[IN], prB[IN];
        #pragma unroll
        for (int m = 0; m < IN; m++) {
            ull accA = 0, accB = 0;
            const float* fr = fcw + m * H;
            #pragma unroll
            for (int p = 0; p < 16; p++) {     // 16 chunks of 16B over 64 floats
                ulonglong2 q = *(const ulonglong2*)(fr + 4 * p);
                ffma2(accA, sA[5 + 2*p], q.x); ffma2(accA, sA[5 + 2*p + 1], q.y);
                ffma2(accB, sB[5 + 2*p], q.x); ffma2(accB, sB[5 + 2*p + 1], q.y);
            }
            prA[m] = psum(accA) + fcb[m];
            prB[m] = psum(accB) + fcb[m];
            outA[t * IN + m] = prA[m];
            outB[t * IN + m] = prB[m];
        }
        sA[0] = pack2(prA[0], prA[1]); sA[1] = pack2(prA[2], prA[3]);
        sA[2] = pack2(prA[4], prA[5]); sA[3] = pack2(prA[6], prA[7]);
        sA[4] = pack2(prA[8], 1.0f);
        sB[0] = pack2(prB[0], prB[1]); sB[1] = pack2(prB[2], prB[3]);
        sB[2] = pack2(prB[4], prB[5]); sB[3] = pack2(prB[6], prB[7]);
        sB[4] = pack2(prB[8], 1.0f);
    }
}

extern "C" void kernel_launch(void* const* d_in, const int* in_sizes, int n_in,
                              void* d_out, int out_size)
{
    const float* src  = (const float*)d_in[0];
    const float* eWih = (const float*)d_in[1];
    const float* eWhh = (const float*)d_in[2];
    const float* eb   = (const float*)d_in[3];
    const float* dWih = (const float*)d_in[4];
    const float* dWhh = (const float*)d_in[5];
    const float* db   = (const float*)d_in[6];
    const float* fcW  = (const float*)d_in[7];
    const float* fcb  = (const float*)d_in[8];
    float* out = (float*)d_out;

    cudaFuncSetAttribute(lstm_seq2seq_kernel,
                         cudaFuncAttributeMaxDynamicSharedMemorySize, SMEM_BYTES);

    lstm_seq2seq_kernel<<<BTOT / EPB, TPB, SMEM_BYTES>>>(
        src, eWih, eWhh, eb, dWih, dWhh, db, fcW, fcb, out);
}

// round 11
// speedup vs baseline: 2.1717x; 2.1717x over previous
#include <cuda_runtime.h>
#include <cuda_bf16.h>
#include <cstdint>

// LSTM seq2seq via mma.sync (HMMA bf16, portable sm_103):
//   gates[256, 64b] = W[256, 80] @ state[64b, 80]^T, hi/lo bf16 split (3 passes)
// Weights live in A fragments (registers, loaded once per phase).
// m = 4*j + gate, K = [h(64) | x(9) | 1 | pad(6)].

#define SRCLEN 7
#define PREDLEN 10
#define NSTEPS 17
#define IN_ 9
#define H_ 64
#define TPB 256
#define BPC 64          // batch rows per CTA
#define GRID 1024

// smem layout (bytes)
#define SB_SHI 0                         // state hi: 64 rows x 88 bf16 (176B)
#define SB_SLO 11264                     // state lo
#define SB_G   22528                     // gate buf: 256 rows x 68 f32 (272B)
#define SB_FCW (22528 + 69632)           // 92160: fc weights 9x64 f32
#define SB_FCB (SB_FCW + 2304)           // 94464
#define SB_P   (SB_FCB + 64)             // 94528: FC partials 64 x 36 f32 (144B)
#define SMEM_BYTES (SB_P + 9216)         // 103744

typedef unsigned int u32;

__device__ __forceinline__ float fast_tanh(float x) {
    float y; asm("tanh.approx.f32 %0, %1;" : "=f"(y) : "f"(x)); return y;
}
__device__ __forceinline__ float fast_sigmoid(float x) { return fmaf(0.5f, fast_tanh(0.5f * x), 0.5f); }
__device__ __forceinline__ u32 pk(float a, float b) {
    __nv_bfloat162 t = __floats2bfloat162_rn(a, b); return *reinterpret_cast<u32*>(&t);
}
__device__ __forceinline__ float bfhi(float v) { return __bfloat162float(__float2bfloat16(v)); }
__device__ __forceinline__ void split2(float a, float b, u32 &hi, u32 &lo) {
    float ah = bfhi(a), bh = bfhi(b);
    hi = pk(a, b); lo = pk(a - ah, b - bh);
}

#define MMA4(d, a, b0, b1) asm volatile( \
    "mma.sync.aligned.m16n8k16.row.col.f32.bf16.bf16.f32 " \
    "{%0,%1,%2,%3},{%4,%5,%6,%7},{%8,%9},{%0,%1,%2,%3};" \
    : "+f"((d)[0]), "+f"((d)[1]), "+f"((d)[2]), "+f"((d)[3]) \
    : "r"((a)[0]), "r"((a)[1]), "r"((a)[2]), "r"((a)[3]), "r"(b0), "r"(b1))

// fused weight element: row m = 4j+g -> source row wr = g*64+j
__device__ __forceinline__ float welem(const float* __restrict__ Wih,
                                       const float* __restrict__ Whh,
                                       const float* __restrict__ bias, int m, int k) {
    int j = m >> 2, g = m & 3, wr = g * 64 + j;
    if (k < 64) return Whh[wr * 64 + k];
    if (k < 73) return Wih[wr * 9 + (k - 64)];
    if (k == 73) return bias[wr];
    return 0.0f;
}

// Load A fragments: warp owns M-tiles {2w, 2w+1}; per tile 5 K-chunks x 4 regs.
// m16n8k16 A frag: q0:(r, k0), q1:(r+8, k0), q2:(r, k0+8), q3:(r+8, k0+8);
// r = lane/4, k0 = 2*(lane%4), each reg = 2 bf16 along k.
__device__ void load_A(u32 ah[2][5][4], u32 al[2][5][4],
                       const float* __restrict__ Wih, const float* __restrict__ Whh,
                       const float* __restrict__ bias, int wid, int lane) {
    int g4 = lane >> 2, t4 = lane & 3;
    #pragma unroll
    for (int i = 0; i < 2; i++) {
        int mt = wid * 2 + i;
        #pragma unroll
        for (int kc = 0; kc < 5; kc++)
            #pragma unroll
            for (int q = 0; q < 4; q++) {
                int m = 16 * mt + g4 + (q & 1) * 8;
                int k = 16 * kc + 2 * t4 + (q >> 1) * 8;
                float v0 = welem(Wih, Whh, bias, m, k);
                float v1 = welem(Wih, Whh, bias, m, k + 1);
                split2(v0, v1, ah[i][kc][q], al[i][kc][q]);
            }
    }
}

__global__ void __launch_bounds__(TPB, 1)
lstm_mma(const float* __restrict__ src,
         const float* __restrict__ eWih, const float* __restrict__ eWhh, const float* __restrict__ eb,
         const float* __restrict__ dWih, const float* __restrict__ dWhh, const float* __restrict__ db,
         const float* __restrict__ fcW, const float* __restrict__ fcb, float* __restrict__ out)
{
    extern __shared__ char sm[];
    const int tid = threadIdx.x;
    const int wid = tid >> 5, lane = tid & 31;
    const int g4 = lane >> 2, t4 = lane & 3;
    const int base = blockIdx.x * BPC;
    const int bme = tid & 63;            // epilogue batch row
    const int jg  = tid >> 6;            // epilogue j-group (16 j's)

    // ---- zero state buffers ----
    for (int i = tid; i < 2816; i += TPB) {
        ((u32*)(sm + SB_SHI))[i] = 0u;
        ((u32*)(sm + SB_SLO))[i] = 0u;
    }
    __syncthreads();
    // x0 + "one" at k=73
    if (tid < BPC) {
        #pragma unroll
        for (int k = 0; k < IN_; k++) {
            float v = src[(size_t)(base + tid) * (SRCLEN * IN_) + k];
            float vh = bfhi(v);
            *(__nv_bfloat16*)(sm + SB_SHI + tid * 176 + (64 + k) * 2) = __float2bfloat16(vh);
            *(__nv_bfloat16*)(sm + SB_SLO + tid * 176 + (64 + k) * 2) = __float2bfloat16(v - vh);
        }
        *(__nv_bfloat16*)(sm + SB_SHI + tid * 176 + 73 * 2) = __float2bfloat16(1.0f);
    }

    u32 ah[2][5][4], al[2][5][4];
    load_A(ah, al, eWih, eWhh, eb, wid, lane);

    float cc[16];
    #pragma unroll
    for (int i = 0; i < 16; i++) cc[i] = 0.0f;
    __syncthreads();

    #pragma unroll 1
    for (int t = 0; t < NSTEPS; t++) {
        const bool dec = (t >= SRCLEN);

        // encoder: prefetch next x early (latency hidden under MMA)
        float xr[IN_];
        if (t < SRCLEN - 1 && tid < BPC) {
            #pragma unroll
            for (int k = 0; k < IN_; k++)
                xr[k] = src[(size_t)(base + tid) * (SRCLEN * IN_) + (t + 1) * IN_ + k];
        }

        // ---- phase A: MMA ----
        const int boff = (g4) * 176 + (2 * t4) * 2;   // + nt*8*176 + kc*32
        #pragma unroll
        for (int nt = 0; nt < 8; nt++) {
            u32 bh[5][2], bl[5][2];
            const char* ph = sm + SB_SHI + nt * 8 * 176 + boff;
            const char* pl = sm + SB_SLO + nt * 8 * 176 + boff;
            #pragma unroll
            for (int kc = 0; kc < 5; kc++) {
                bh[kc][0] = *(const u32*)(ph + kc * 32);
                bh[kc][1] = *(const u32*)(ph + kc * 32 + 16);
                bl[kc][0] = *(const u32*)(pl + kc * 32);
                bl[kc][1] = *(const u32*)(pl + kc * 32 + 16);
            }
            #pragma unroll
            for (int i = 0; i < 2; i++) {
                float d[4] = {0.f, 0.f, 0.f, 0.f};
                #pragma unroll
                for (int kc = 0; kc < 5; kc++) MMA4(d, ah[i][kc], bh[kc][0], bh[kc][1]);
                #pragma unroll
                for (int kc = 0; kc < 5; kc++) MMA4(d, ah[i][kc], bl[kc][0], bl[kc][1]);
                #pragma unroll
                for (int kc = 0; kc < 5; kc++) MMA4(d, al[i][kc], bh[kc][0], bh[kc][1]);
                int row = 16 * (2 * wid + i) + g4;
                int col = 8 * nt + 2 * t4;
                *(float2*)(sm + SB_G + (size_t)row * 272 + col * 4)       = make_float2(d[0], d[1]);
                *(float2*)(sm + SB_G + (size_t)(row + 8) * 272 + col * 4) = make_float2(d[2], d[3]);
            }
        }
        __syncthreads();   // (1) gates visible; state reads done

        // ---- phase B: activations, c/h update ----
        const float* gr = (const float*)(sm + SB_G);
        float hloc[16];
        #pragma unroll
        for (int jj = 0; jj < 16; jj++) {
            int j = jg * 16 + jj;
            float gi = gr[(4 * j + 0) * 68 + bme];
            float gf = gr[(4 * j + 1) * 68 + bme];
            float gg = gr[(4 * j + 2) * 68 + bme];
            float go = gr[(4 * j + 3) * 68 + bme];
            float ii = fast_sigmoid(gi);
            float ff = fast_sigmoid(gf);
            float g_ = fast_tanh(gg);
            float oo = fast_sigmoid(go);
            float cn = fmaf(ff, cc[jj], ii * g_);
            cc[jj] = cn;
            hloc[jj] = oo * fast_tanh(cn);
        }
        // h -> state buf (hi/lo pairs)
        #pragma unroll
        for (int p = 0; p < 8; p++) {
            int j0 = jg * 16 + 2 * p;
            u32 hw, lw; split2(hloc[2 * p], hloc[2 * p + 1], hw, lw);
            *(u32*)(sm + SB_SHI + bme * 176 + j0 * 2) = hw;
            *(u32*)(sm + SB_SLO + bme * 176 + j0 * 2) = lw;
        }
        // encoder next-x write
        if (t < SRCLEN - 1 && tid < BPC) {
            #pragma unroll
            for (int k = 0; k < IN_; k++) {
                float vh = bfhi(xr[k]);
                *(__nv_bfloat16*)(sm + SB_SHI + tid * 176 + (64 + k) * 2) = __float2bfloat16(vh);
                *(__nv_bfloat16*)(sm + SB_SLO + tid * 176 + (64 + k) * 2) = __float2bfloat16(xr[k] - vh);
            }
        }
        // decoder: distributed FC partials (over this thread's 16 h's)
        if (dec) {
            const float* fw = (const float*)(sm + SB_FCW);
            float pa[IN_];
            #pragma unroll
            for (int m = 0; m < IN_; m++) pa[m] = 0.0f;
            #pragma unroll
            for (int jj = 0; jj < 16; jj++) {
                float hv = hloc[jj]; int j = jg * 16 + jj;
                #pragma unroll
                for (int m = 0; m < IN_; m++) pa[m] = fmaf(hv, fw[m * 64 + j], pa[m]);
            }
            float* pb = (float*)(sm + SB_P);
            #pragma unroll
            for (int m = 0; m < IN_; m++) pb[bme * 36 + jg * 9 + m] = pa[m];
        }
        __syncthreads();   // (2) h/x/partials ready

        if (dec) {
            if (tid < BPC) {
                const float* pb = (const float*)(sm + SB_P);
                const float* fb = (const float*)(sm + SB_FCB);
                #pragma unroll
                for (int m = 0; m < IN_; m++) {
                    float pr = fb[m] + pb[tid * 36 + m] + pb[tid * 36 + 9 + m]
                             + pb[tid * 36 + 18 + m] + pb[tid * 36 + 27 + m];
                    out[(size_t)(base + tid) * (PREDLEN * IN_) + (t - SRCLEN) * IN_ + m] = pr;
                    float ph2 = bfhi(pr);
                    *(__nv_bfloat16*)(sm + SB_SHI + tid * 176 + (64 + m) * 2) = __float2bfloat16(ph2);
                    *(__nv_bfloat16*)(sm + SB_SLO + tid * 176 + (64 + m) * 2) = __float2bfloat16(pr - ph2);
                }
            }
            __syncthreads();   // (3) next x ready
        }

        if (t == SRCLEN - 1) {   // swap to decoder weights + FC into smem
            load_A(ah, al, dWih, dWhh, db, wid, lane);
            for (int i = tid; i < IN_ * H_; i += TPB) ((float*)(sm + SB_FCW))[i] = fcW[i];
            if (tid < IN_) ((float*)(sm + SB_FCB))[tid] = fcb[tid];
            __syncthreads();
        }
    }
}

extern "C" void kernel_launch(void* const* d_in, const int* in_sizes, int n_in,
                              void* d_out, int out_size)
{
    cudaFuncSetAttribute(lstm_mma, cudaFuncAttributeMaxDynamicSharedMemorySize, SMEM_BYTES);
    lstm_mma<<<GRID, TPB, SMEM_BYTES>>>(
        (const float*)d_in[0], (const float*)d_in[1], (const float*)d_in[2],
        (const float*)d_in[3], (const float*)d_in[4], (const float*)d_in[5],
        (const float*)d_in[6], (const float*)d_in[7], (const float*)d_in[8],
        (float*)d_out);
}